// round 1
// baseline (speedup 1.0000x reference)
#include <cuda_runtime.h>

#define D_    1024
#define H_    16
#define DH    64
#define NL_   2
#define NE    8
#define HID_  4096
#define KCB   8192
#define LLEV  3
#define BB    8
#define TT    128
#define TEN   256
#define NTOK  (BB*TT)    /* 1024 */
#define NKV   (BB*TEN)   /* 2048 */

// ---------------- scratch (device globals; no allocation) ----------------
__device__ float g_x [NTOK*D_];
__device__ float g_xn[NTOK*D_];
__device__ float g_q [NTOK*D_];
__device__ float g_k [NKV*D_];
__device__ float g_v [NKV*D_];
__device__ float g_ao[NTOK*D_];
__device__ float g_h [NTOK*HID_];
__device__ float g_gw[NE*NTOK];
__device__ int   g_cnt[NE];
__device__ int   g_idx[NE*NTOK];

// ---------------- embed gather ----------------
__global__ void embed_k(const int* __restrict__ ids, const float* __restrict__ emb) {
    int i = blockIdx.x * 256 + threadIdx.x;   // over NTOK * (D_/4)
    int n = i >> 8;                           // D_/4 = 256
    int c = i & 255;
    const float4* src = (const float4*)(emb + (size_t)ids[n] * D_) + c;
    ((float4*)g_x)[i] = *src;
}

// ---------------- rmsnorm ----------------
__global__ void rmsnorm_k(const float* __restrict__ x, const float* __restrict__ w,
                          float* __restrict__ out) {
    int row = blockIdx.x;
    int tid = threadIdx.x;  // 256
    const float* xr = x + (size_t)row * D_;
    float ss = 0.f;
    for (int i = tid; i < D_; i += 256) { float v = xr[i]; ss += v * v; }
    __shared__ float red[256];
    red[tid] = ss; __syncthreads();
    for (int s = 128; s > 0; s >>= 1) {
        if (tid < s) red[tid] += red[tid + s];
        __syncthreads();
    }
    float scale = rsqrtf(red[0] * (1.0f / D_) + 1e-6f);
    for (int i = tid; i < D_; i += 256)
        out[(size_t)row * D_ + i] = xr[i] * scale * w[i];
}

// ---------------- generic SGEMM: C[M,Nn] = A[M,K] * W[Nn,K]^T (+C) ----------------
// 128x128 tile, BK=8, 256 threads, 8x8 microtile. M,Nn multiples of 128; K mult of 8.
template <int ADD>
__global__ void gemm128(const float* __restrict__ A, const float* __restrict__ Wt,
                        float* __restrict__ C, int M, int Nn, int K) {
    __shared__ float As[8][128];
    __shared__ float Bs[8][128];
    const int bm = blockIdx.y * 128, bn = blockIdx.x * 128;
    const int tid = threadIdx.x;
    const int lr = tid >> 1;            // 0..127
    const int lc = (tid & 1) << 2;      // 0 or 4
    const int tm = (tid >> 4) << 3;
    const int tn = (tid & 15) << 3;
    float acc[8][8];
    #pragma unroll
    for (int i = 0; i < 8; i++)
        #pragma unroll
        for (int j = 0; j < 8; j++) acc[i][j] = 0.f;

    const float* Ap = A  + (size_t)(bm + lr) * K + lc;
    const float* Bp = Wt + (size_t)(bn + lr) * K + lc;
    for (int k0 = 0; k0 < K; k0 += 8) {
        float4 a = *(const float4*)(Ap + k0);
        float4 b = *(const float4*)(Bp + k0);
        As[lc + 0][lr] = a.x; As[lc + 1][lr] = a.y; As[lc + 2][lr] = a.z; As[lc + 3][lr] = a.w;
        Bs[lc + 0][lr] = b.x; Bs[lc + 1][lr] = b.y; Bs[lc + 2][lr] = b.z; Bs[lc + 3][lr] = b.w;
        __syncthreads();
        #pragma unroll
        for (int k = 0; k < 8; k++) {
            float ra[8], rb[8];
            #pragma unroll
            for (int i = 0; i < 8; i++) ra[i] = As[k][tm + i];
            #pragma unroll
            for (int j = 0; j < 8; j++) rb[j] = Bs[k][tn + j];
            #pragma unroll
            for (int i = 0; i < 8; i++)
                #pragma unroll
                for (int j = 0; j < 8; j++) acc[i][j] += ra[i] * rb[j];
        }
        __syncthreads();
    }
    #pragma unroll
    for (int i = 0; i < 8; i++) {
        float* Cp = C + (size_t)(bm + tm + i) * Nn + bn + tn;
        #pragma unroll
        for (int j = 0; j < 8; j++) {
            if (ADD) Cp[j] += acc[i][j];
            else     Cp[j]  = acc[i][j];
        }
    }
}

// ---------------- fused attention (one block per (b,h,tq)) ----------------
__global__ void attn_k(const float* __restrict__ q, const float* __restrict__ kk,
                       const float* __restrict__ vv, float* __restrict__ out,
                       int Tk, int causal) {
    int b = blockIdx.z, h = blockIdx.y, tq = blockIdx.x;
    int tid = threadIdx.x;  // 128
    __shared__ float sq[DH];
    __shared__ float sc[TEN];
    __shared__ float red[128];
    const float* qp = q + (size_t)(b * TT + tq) * D_ + h * DH;
    if (tid < DH) sq[tid] = qp[tid];
    __syncthreads();
    int lim = causal ? (tq + 1) : Tk;
    for (int j = tid; j < Tk; j += 128) {
        float s = -1e30f;
        if (j < lim) {
            const float* kp = kk + (size_t)(b * Tk + j) * D_ + h * DH;
            float dot = 0.f;
            #pragma unroll
            for (int d = 0; d < DH; d++) dot += sq[d] * kp[d];
            s = dot * 0.125f;  // dh^-0.5
        }
        sc[j] = s;
    }
    __syncthreads();
    float m = -1e30f;
    for (int j = tid; j < Tk; j += 128) m = fmaxf(m, sc[j]);
    red[tid] = m; __syncthreads();
    for (int s2 = 64; s2 > 0; s2 >>= 1) {
        if (tid < s2) red[tid] = fmaxf(red[tid], red[tid + s2]);
        __syncthreads();
    }
    float mx = red[0];
    __syncthreads();
    float ssum = 0.f;
    for (int j = tid; j < Tk; j += 128) { float e = __expf(sc[j] - mx); sc[j] = e; ssum += e; }
    red[tid] = ssum; __syncthreads();
    for (int s2 = 64; s2 > 0; s2 >>= 1) {
        if (tid < s2) red[tid] += red[tid + s2];
        __syncthreads();
    }
    float inv = 1.0f / red[0];
    __syncthreads();
    if (tid < DH) {
        float o = 0.f;
        for (int j = 0; j < lim; j++)
            o += sc[j] * vv[(size_t)(b * Tk + j) * D_ + h * DH + tid];
        out[(size_t)(b * TT + tq) * D_ + h * DH + tid] = o * inv;
    }
}

// ---------------- router: top-2 + gate weights + expert token lists ----------------
__global__ void reset_cnt_k() { if (threadIdx.x < NE) g_cnt[threadIdx.x] = 0; }

__global__ void router_k(const float* __restrict__ xn, const float* __restrict__ rw) {
    int n = blockIdx.x;
    int tid = threadIdx.x;      // 256 = 8 warps = NE experts
    int w = tid >> 5, lane = tid & 31;
    const float* xr = xn + (size_t)n * D_;
    const float* wr = rw + (size_t)w * D_;
    float dot = 0.f;
    for (int i = lane; i < D_; i += 32) dot += xr[i] * wr[i];
    #pragma unroll
    for (int o = 16; o > 0; o >>= 1) dot += __shfl_down_sync(0xffffffffu, dot, o);
    __shared__ float lg[NE];
    if (lane == 0) lg[w] = dot;
    __syncthreads();
    if (tid == 0) {
        int i1 = 0; float v1 = lg[0];
        for (int e = 1; e < NE; e++) if (lg[e] > v1) { v1 = lg[e]; i1 = e; }
        int i2 = -1; float v2 = -1e30f;
        for (int e = 0; e < NE; e++) {
            if (e == i1) continue;
            if (lg[e] > v2) { v2 = lg[e]; i2 = e; }
        }
        float e2 = __expf(v2 - v1);
        float w1 = 1.f / (1.f + e2);
        float w2 = e2 / (1.f + e2);
        g_gw[i1 * NTOK + n] = w1;
        g_gw[i2 * NTOK + n] = w2;
        int p1 = atomicAdd(&g_cnt[i1], 1); g_idx[i1 * NTOK + p1] = n;
        int p2 = atomicAdd(&g_cnt[i2], 1); g_idx[i2 * NTOK + p2] = n;
    }
}

// ---------------- MoE: gathered gate+up fused (64x64x16, dual acc) ----------------
__global__ void moe_gateup_k(const float* __restrict__ xn, const float* __restrict__ wg,
                             const float* __restrict__ wu, int e) {
    int cnt = g_cnt[e];
    int bm = blockIdx.y * 64;
    if (bm >= cnt) return;
    int bn = blockIdx.x * 64;
    int tid = threadIdx.x;  // 256
    int lr = tid >> 2;           // 0..63
    int lc = (tid & 3) << 2;     // 0,4,8,12
    int tm = (tid >> 4) << 2;
    int tn = (tid & 15) << 2;
    __shared__ float As[16][64];
    __shared__ float Bg[16][64];
    __shared__ float Bu[16][64];
    int r = bm + lr;
    int rc = r < cnt ? r : (cnt - 1);
    int tok = g_idx[e * NTOK + rc];
    const float* Ap = xn + (size_t)tok * D_ + lc;
    const float* Gp = wg + (size_t)(bn + lr) * D_ + lc;
    const float* Up = wu + (size_t)(bn + lr) * D_ + lc;
    float ag[4][4], au[4][4];
    #pragma unroll
    for (int i = 0; i < 4; i++)
        #pragma unroll
        for (int j = 0; j < 4; j++) { ag[i][j] = 0.f; au[i][j] = 0.f; }

    for (int k0 = 0; k0 < D_; k0 += 16) {
        float4 a  = *(const float4*)(Ap + k0);
        float4 bg = *(const float4*)(Gp + k0);
        float4 bu = *(const float4*)(Up + k0);
        As[lc + 0][lr] = a.x;  As[lc + 1][lr] = a.y;  As[lc + 2][lr] = a.z;  As[lc + 3][lr] = a.w;
        Bg[lc + 0][lr] = bg.x; Bg[lc + 1][lr] = bg.y; Bg[lc + 2][lr] = bg.z; Bg[lc + 3][lr] = bg.w;
        Bu[lc + 0][lr] = bu.x; Bu[lc + 1][lr] = bu.y; Bu[lc + 2][lr] = bu.z; Bu[lc + 3][lr] = bu.w;
        __syncthreads();
        #pragma unroll
        for (int k = 0; k < 16; k++) {
            float ra[4], rg[4], ru[4];
            #pragma unroll
            for (int i = 0; i < 4; i++) ra[i] = As[k][tm + i];
            #pragma unroll
            for (int j = 0; j < 4; j++) { rg[j] = Bg[k][tn + j]; ru[j] = Bu[k][tn + j]; }
            #pragma unroll
            for (int i = 0; i < 4; i++)
                #pragma unroll
                for (int j = 0; j < 4; j++) {
                    ag[i][j] += ra[i] * rg[j];
                    au[i][j] += ra[i] * ru[j];
                }
        }
        __syncthreads();
    }
    #pragma unroll
    for (int i = 0; i < 4; i++) {
        int rr = bm + tm + i;
        if (rr < cnt) {
            float* hp = g_h + (size_t)rr * HID_ + bn + tn;
            #pragma unroll
            for (int j = 0; j < 4; j++) {
                float g = ag[i][j];
                float s = g / (1.f + __expf(-g));   // silu
                hp[j] = s * au[i][j];
            }
        }
    }
}

// ---------------- MoE: down-proj with scatter-add + gate scale (64x64x16) ----------------
__global__ void moe_down_k(const float* __restrict__ wd, int e) {
    int cnt = g_cnt[e];
    int bm = blockIdx.y * 64;
    if (bm >= cnt) return;
    int bn = blockIdx.x * 64;     // over D_/64 = 16
    int tid = threadIdx.x;
    int lr = tid >> 2;
    int lc = (tid & 3) << 2;
    int tm = (tid >> 4) << 2;
    int tn = (tid & 15) << 2;
    __shared__ float As[16][64];
    __shared__ float Bs[16][64];
    const float* Ap = g_h + (size_t)(bm + lr) * HID_ + lc;
    const float* Bp = wd  + (size_t)(bn + lr) * HID_ + lc;
    float acc[4][4];
    #pragma unroll
    for (int i = 0; i < 4; i++)
        #pragma unroll
        for (int j = 0; j < 4; j++) acc[i][j] = 0.f;

    for (int k0 = 0; k0 < HID_; k0 += 16) {
        float4 a = *(const float4*)(Ap + k0);
        float4 b = *(const float4*)(Bp + k0);
        As[lc + 0][lr] = a.x; As[lc + 1][lr] = a.y; As[lc + 2][lr] = a.z; As[lc + 3][lr] = a.w;
        Bs[lc + 0][lr] = b.x; Bs[lc + 1][lr] = b.y; Bs[lc + 2][lr] = b.z; Bs[lc + 3][lr] = b.w;
        __syncthreads();
        #pragma unroll
        for (int k = 0; k < 16; k++) {
            float ra[4], rb[4];
            #pragma unroll
            for (int i = 0; i < 4; i++) ra[i] = As[k][tm + i];
            #pragma unroll
            for (int j = 0; j < 4; j++) rb[j] = Bs[k][tn + j];
            #pragma unroll
            for (int i = 0; i < 4; i++)
                #pragma unroll
                for (int j = 0; j < 4; j++) acc[i][j] += ra[i] * rb[j];
        }
        __syncthreads();
    }
    #pragma unroll
    for (int i = 0; i < 4; i++) {
        int rr = bm + tm + i;
        if (rr < cnt) {
            int tok = g_idx[e * NTOK + rr];
            float scale = g_gw[e * NTOK + tok];
            float* xp = g_x + (size_t)tok * D_ + bn + tn;
            #pragma unroll
            for (int j = 0; j < 4; j++) xp[j] += scale * acc[i][j];
        }
    }
}

// ---------------- host orchestration ----------------
extern "C" void kernel_launch(void* const* d_in, const int* in_sizes, int n_in,
                              void* d_out, int out_size) {
    const int*   ids  = (const int*)d_in[0];
    const float* enc  = (const float*)d_in[1];
    const float* emb  = (const float*)d_in[2];
    const float* n1   = (const float*)d_in[3];
    const float* n2   = (const float*)d_in[4];
    const float* n3   = (const float*)d_in[5];
    const float* wq_s = (const float*)d_in[6];
    const float* wk_s = (const float*)d_in[7];
    const float* wv_s = (const float*)d_in[8];
    const float* wo_s = (const float*)d_in[9];
    const float* wq_c = (const float*)d_in[10];
    const float* wk_c = (const float*)d_in[11];
    const float* wv_c = (const float*)d_in[12];
    const float* wo_c = (const float*)d_in[13];
    const float* rw   = (const float*)d_in[14];
    const float* wg   = (const float*)d_in[15];
    const float* wu   = (const float*)d_in[16];
    const float* wd   = (const float*)d_in[17];
    const float* fn   = (const float*)d_in[18];
    const float* hw   = (const float*)d_in[19];
    float* out = (float*)d_out;

    float *x, *xn, *q, *k, *v, *ao;
    cudaGetSymbolAddress((void**)&x,  g_x);
    cudaGetSymbolAddress((void**)&xn, g_xn);
    cudaGetSymbolAddress((void**)&q,  g_q);
    cudaGetSymbolAddress((void**)&k,  g_k);
    cudaGetSymbolAddress((void**)&v,  g_v);
    cudaGetSymbolAddress((void**)&ao, g_ao);

    const size_t DD = (size_t)D_ * D_;

    embed_k<<<NTOK, 256>>>(ids, emb);

    for (int l = 0; l < NL_; l++) {
        // ---- self attention ----
        rmsnorm_k<<<NTOK, 256>>>(x, n1 + l * D_, xn);
        gemm128<0><<<dim3(8, 8), 256>>>(xn, wq_s + l * DD, q, NTOK, D_, D_);
        gemm128<0><<<dim3(8, 8), 256>>>(xn, wk_s + l * DD, k, NTOK, D_, D_);
        gemm128<0><<<dim3(8, 8), 256>>>(xn, wv_s + l * DD, v, NTOK, D_, D_);
        attn_k<<<dim3(TT, H_, BB), 128>>>(q, k, v, ao, TT, 1);
        gemm128<1><<<dim3(8, 8), 256>>>(ao, wo_s + l * DD, x, NTOK, D_, D_);

        // ---- cross attention ----
        rmsnorm_k<<<NTOK, 256>>>(x, n2 + l * D_, xn);
        gemm128<0><<<dim3(8, 8),  256>>>(xn,  wq_c + l * DD, q, NTOK, D_, D_);
        gemm128<0><<<dim3(8, 16), 256>>>(enc, wk_c + l * DD, k, NKV,  D_, D_);
        gemm128<0><<<dim3(8, 16), 256>>>(enc, wv_c + l * DD, v, NKV,  D_, D_);
        attn_k<<<dim3(TT, H_, BB), 128>>>(q, k, v, ao, TEN, 0);
        gemm128<1><<<dim3(8, 8), 256>>>(ao, wo_c + l * DD, x, NTOK, D_, D_);

        // ---- MoE (gathered: only selected tokens per expert) ----
        rmsnorm_k<<<NTOK, 256>>>(x, n3 + l * D_, xn);
        reset_cnt_k<<<1, 32>>>();
        router_k<<<NTOK, 256>>>(xn, rw + (size_t)l * NE * D_);
        for (int e = 0; e < NE; e++) {
            size_t off = (size_t)(l * NE + e) * HID_ * D_;
            moe_gateup_k<<<dim3(HID_ / 64, NTOK / 64), 256>>>(xn, wg + off, wu + off, e);
            moe_down_k<<<dim3(D_ / 64, NTOK / 64), 256>>>(wd + off, e);
        }
    }

    // ---- final norm + heads ----
    rmsnorm_k<<<NTOK, 256>>>(x, fn, xn);
    for (int l = 0; l < LLEV; l++) {
        gemm128<0><<<dim3(KCB / 128, NTOK / 128), 256>>>(
            xn, hw + (size_t)l * KCB * D_, out + (size_t)l * NTOK * KCB,
            NTOK, KCB, D_);
    }
}

// round 3
// speedup vs baseline: 1.2735x; 1.2735x over previous
#include <cuda_runtime.h>

#define D_    1024
#define H_    16
#define DH    64
#define NL_   2
#define NE    8
#define HID_  4096
#define KCB   8192
#define LLEV  3
#define BB    8
#define TT    128
#define TEN   256
#define NTOK  (BB*TT)    /* 1024 */
#define NKV   (BB*TEN)   /* 2048 */

// ---------------- scratch (device globals; no allocation) ----------------
__device__ float g_x [NTOK*D_];
__device__ float g_xn[NTOK*D_];
__device__ float g_q [NTOK*D_];
__device__ float g_k [NKV*D_];
__device__ float g_v [NKV*D_];
__device__ float g_ao[NTOK*D_];
__device__ float g_h2[(size_t)NE*NTOK*HID_];   // per-expert hidden
__device__ float g_gw[NE*NTOK];
__device__ int   g_cnt[NE];
__device__ int   g_idx[NE*NTOK];

// ---------------- tf32 helpers ----------------
__device__ __forceinline__ unsigned f2tf(float x) {
    unsigned u; asm("cvt.rna.tf32.f32 %0, %1;" : "=r"(u) : "f"(x)); return u;
}
__device__ __forceinline__ void split2(float v, unsigned& hi, unsigned& lo) {
    unsigned h = f2tf(v);
    hi = h;
    lo = f2tf(v - __uint_as_float(h));   // residual exact in fp32
}
__device__ __forceinline__ void mma8(float4& d, const uint4& a, const uint2& b) {
    asm volatile("mma.sync.aligned.m16n8k8.row.col.f32.tf32.tf32.f32 "
                 "{%0,%1,%2,%3}, {%4,%5,%6,%7}, {%8,%9}, {%0,%1,%2,%3};"
                 : "+f"(d.x), "+f"(d.y), "+f"(d.z), "+f"(d.w)
                 : "r"(a.x), "r"(a.y), "r"(a.z), "r"(a.w), "r"(b.x), "r"(b.y));
}
// permuted smem stores: A-frag = one conflict-free 128b LDS, B-frag = one 64b LDS
__device__ __forceinline__ void stsA2(uint4* Ah, uint4* Al, int m, int k, float v) {
    int slot = ((m >> 4) * 4 + (k >> 3)) * 32 + ((m & 7) * 4 + (k & 3));
    int idx  = ((k & 4) >> 1) | ((m >> 3) & 1);
    unsigned hi, lo; split2(v, hi, lo);
    ((unsigned*)(Ah + slot))[idx] = hi;
    ((unsigned*)(Al + slot))[idx] = lo;
}
__device__ __forceinline__ void stsB2(uint2* Bh, uint2* Bl, int n, int k, float v) {
    int slot = ((n >> 3) * 4 + (k >> 3)) * 32 + ((n & 7) * 4 + (k & 3));
    int idx  = (k >> 2) & 1;
    unsigned hi, lo; split2(v, hi, lo);
    ((unsigned*)(Bh + slot))[idx] = hi;
    ((unsigned*)(Bl + slot))[idx] = lo;
}
#define STS4A2(bh, bl, m, k, f4) do { stsA2(bh, bl, m, (k)+0, (f4).x); stsA2(bh, bl, m, (k)+1, (f4).y); \
                                      stsA2(bh, bl, m, (k)+2, (f4).z); stsA2(bh, bl, m, (k)+3, (f4).w); } while(0)
#define STS4B2(bh, bl, n, k, f4) do { stsB2(bh, bl, n, (k)+0, (f4).x); stsB2(bh, bl, n, (k)+1, (f4).y); \
                                      stsB2(bh, bl, n, (k)+2, (f4).z); stsB2(bh, bl, n, (k)+3, (f4).w); } while(0)

// triple-MMA: hi*hi + lo*hi + hi*lo  (fp32-accurate, lo*lo ~2^-22 dropped)
#define MMA3(acc, ah, al, bh, bl) do { mma8(acc, ah, bh); mma8(acc, al, bh); mma8(acc, ah, bl); } while(0)

// ---------------- generic split-tf32 GEMM: C[M,N] = A[M,K]*W[N,K]^T (+C) ----------------
// 64x64x32 block, 128 threads (4 warps, 32x32 warp tile). M,N mult of 64, K mult of 32.
template <int ADD>
__global__ __launch_bounds__(128)
void gemm_t(const float* __restrict__ A, const float* __restrict__ W,
            float* __restrict__ C, int M, int N, int K) {
    __shared__ uint4 Ah[512], Al[512];
    __shared__ uint2 Bh[1024], Bl[1024];
    const int bm = blockIdx.y * 64, bn = blockIdx.x * 64;
    const int tid = threadIdx.x, lane = tid & 31, warp = tid >> 5;
    const int wm = warp >> 1, wn = warp & 1;
    const int lrow = tid >> 1, kb = (tid & 1) * 16;
    const float* Ar = A + (size_t)(bm + lrow) * K + kb;
    const float* Wr = W + (size_t)(bn + lrow) * K + kb;
    float4 acc[2][4];
    #pragma unroll
    for (int i = 0; i < 2; i++)
        #pragma unroll
        for (int j = 0; j < 4; j++) acc[i][j] = make_float4(0.f, 0.f, 0.f, 0.f);
    float4 ra[4], rb[4];
    #pragma unroll
    for (int i = 0; i < 4; i++) { ra[i] = *(const float4*)(Ar + 4 * i); rb[i] = *(const float4*)(Wr + 4 * i); }
    const int nit = K >> 5;
    for (int it = 0; it < nit; it++) {
        if (it) __syncthreads();
        #pragma unroll
        for (int i = 0; i < 4; i++) { STS4A2(Ah, Al, lrow, kb + 4 * i, ra[i]); STS4B2(Bh, Bl, lrow, kb + 4 * i, rb[i]); }
        __syncthreads();
        if (it + 1 < nit) {
            const float* Ap = Ar + (it + 1) * 32;
            const float* Wp = Wr + (it + 1) * 32;
            #pragma unroll
            for (int i = 0; i < 4; i++) { ra[i] = *(const float4*)(Ap + 4 * i); rb[i] = *(const float4*)(Wp + 4 * i); }
        }
        #pragma unroll
        for (int kt = 0; kt < 4; kt++) {
            uint4 ah[2], al[2]; uint2 bh[4], bl[4];
            #pragma unroll
            for (int mt = 0; mt < 2; mt++) {
                int s = ((wm * 2 + mt) * 4 + kt) * 32 + lane;
                ah[mt] = Ah[s]; al[mt] = Al[s];
            }
            #pragma unroll
            for (int nt = 0; nt < 4; nt++) {
                int s = ((wn * 4 + nt) * 4 + kt) * 32 + lane;
                bh[nt] = Bh[s]; bl[nt] = Bl[s];
            }
            #pragma unroll
            for (int mt = 0; mt < 2; mt++)
                #pragma unroll
                for (int nt = 0; nt < 4; nt++) MMA3(acc[mt][nt], ah[mt], al[mt], bh[nt], bl[nt]);
        }
    }
    const int g = lane >> 2, c2 = (lane & 3) * 2;
    #pragma unroll
    for (int mt = 0; mt < 2; mt++)
        #pragma unroll
        for (int nt = 0; nt < 4; nt++) {
            int row = bm + wm * 32 + mt * 16 + g;
            int col = bn + wn * 32 + nt * 8 + c2;
            float* p0 = C + (size_t)row * N + col;
            float* p1 = C + (size_t)(row + 8) * N + col;
            float4 a = acc[mt][nt];
            if (ADD) { p0[0] += a.x; p0[1] += a.y; p1[0] += a.z; p1[1] += a.w; }
            else { *(float2*)p0 = make_float2(a.x, a.y); *(float2*)p1 = make_float2(a.z, a.w); }
        }
}

// ---------------- MoE gate+up fused split-tf32 (gathered rows, all experts) ----------------
__global__ __launch_bounds__(128)
void moe_gateup_t(const float* __restrict__ xn, const float* __restrict__ wg,
                  const float* __restrict__ wu) {
    const int e = blockIdx.z;
    const int cnt = g_cnt[e];
    const int bm = blockIdx.y * 64;
    if (bm >= cnt) return;
    const int bn = blockIdx.x * 64;
    __shared__ uint4 Ah[512], Al[512];
    __shared__ uint2 Gh[1024], Gl[1024], Uh[1024], Ul[1024];
    const int tid = threadIdx.x, lane = tid & 31, warp = tid >> 5;
    const int wm = warp >> 1, wn = warp & 1;
    const int lrow = tid >> 1, kb = (tid & 1) * 16;
    int r = bm + lrow;
    int rc = r < cnt ? r : (cnt - 1);
    int tok = g_idx[e * NTOK + rc];
    const float* Ar = xn + (size_t)tok * D_ + kb;
    const float* Gr = wg + ((size_t)e * HID_ + bn + lrow) * D_ + kb;
    const float* Ur = wu + ((size_t)e * HID_ + bn + lrow) * D_ + kb;
    float4 ag[2][4], au[2][4];
    #pragma unroll
    for (int i = 0; i < 2; i++)
        #pragma unroll
        for (int j = 0; j < 4; j++) { ag[i][j] = make_float4(0.f,0.f,0.f,0.f); au[i][j] = make_float4(0.f,0.f,0.f,0.f); }
    float4 ra[4], rg[4], ru[4];
    #pragma unroll
    for (int i = 0; i < 4; i++) { ra[i] = *(const float4*)(Ar + 4*i); rg[i] = *(const float4*)(Gr + 4*i); ru[i] = *(const float4*)(Ur + 4*i); }
    const int nit = D_ >> 5;
    for (int it = 0; it < nit; it++) {
        if (it) __syncthreads();
        #pragma unroll
        for (int i = 0; i < 4; i++) {
            STS4A2(Ah, Al, lrow, kb + 4*i, ra[i]);
            STS4B2(Gh, Gl, lrow, kb + 4*i, rg[i]);
            STS4B2(Uh, Ul, lrow, kb + 4*i, ru[i]);
        }
        __syncthreads();
        if (it + 1 < nit) {
            const float* Ap = Ar + (it + 1) * 32;
            const float* Gp = Gr + (it + 1) * 32;
            const float* Up = Ur + (it + 1) * 32;
            #pragma unroll
            for (int i = 0; i < 4; i++) { ra[i] = *(const float4*)(Ap + 4*i); rg[i] = *(const float4*)(Gp + 4*i); ru[i] = *(const float4*)(Up + 4*i); }
        }
        #pragma unroll
        for (int kt = 0; kt < 4; kt++) {
            uint4 ah[2], al[2];
            #pragma unroll
            for (int mt = 0; mt < 2; mt++) {
                int s = ((wm * 2 + mt) * 4 + kt) * 32 + lane;
                ah[mt] = Ah[s]; al[mt] = Al[s];
            }
            #pragma unroll
            for (int nt = 0; nt < 4; nt++) {
                int s = ((wn * 4 + nt) * 4 + kt) * 32 + lane;
                uint2 gh = Gh[s], gl = Gl[s], uh = Uh[s], ul = Ul[s];
                #pragma unroll
                for (int mt = 0; mt < 2; mt++) {
                    MMA3(ag[mt][nt], ah[mt], al[mt], gh, gl);
                    MMA3(au[mt][nt], ah[mt], al[mt], uh, ul);
                }
            }
        }
    }
    const int g = lane >> 2, c2 = (lane & 3) * 2;
    float* hb = g_h2 + (size_t)e * NTOK * HID_;
    #pragma unroll
    for (int mt = 0; mt < 2; mt++)
        #pragma unroll
        for (int nt = 0; nt < 4; nt++) {
            int r0 = bm + wm * 32 + mt * 16 + g;
            int col = bn + wn * 32 + nt * 8 + c2;
            float4 gg = ag[mt][nt], uu = au[mt][nt];
            if (r0 < cnt) {
                float s0 = gg.x / (1.f + __expf(-gg.x));
                float s1 = gg.y / (1.f + __expf(-gg.y));
                *(float2*)(hb + (size_t)r0 * HID_ + col) = make_float2(s0 * uu.x, s1 * uu.y);
            }
            if (r0 + 8 < cnt) {
                float s2 = gg.z / (1.f + __expf(-gg.z));
                float s3 = gg.w / (1.f + __expf(-gg.w));
                *(float2*)(hb + (size_t)(r0 + 8) * HID_ + col) = make_float2(s2 * uu.z, s3 * uu.w);
            }
        }
}

// ---------------- MoE down split-tf32 (all experts, scatter-add into residual) ----------------
__global__ __launch_bounds__(128)
void moe_down_t(const float* __restrict__ wd) {
    const int e = blockIdx.z;
    const int cnt = g_cnt[e];
    const int bm = blockIdx.y * 64;
    if (bm >= cnt) return;
    const int bn = blockIdx.x * 64;
    __shared__ uint4 Ah[512], Al[512];
    __shared__ uint2 Bh[1024], Bl[1024];
    const int tid = threadIdx.x, lane = tid & 31, warp = tid >> 5;
    const int wm = warp >> 1, wn = warp & 1;
    const int lrow = tid >> 1, kb = (tid & 1) * 16;
    int r = bm + lrow;
    int rc = r < cnt ? r : (cnt - 1);
    const float* Ar = g_h2 + ((size_t)e * NTOK + rc) * HID_ + kb;
    const float* Wr = wd + ((size_t)e * D_ + bn + lrow) * HID_ + kb;
    float4 acc[2][4];
    #pragma unroll
    for (int i = 0; i < 2; i++)
        #pragma unroll
        for (int j = 0; j < 4; j++) acc[i][j] = make_float4(0.f, 0.f, 0.f, 0.f);
    float4 ra[4], rb[4];
    #pragma unroll
    for (int i = 0; i < 4; i++) { ra[i] = *(const float4*)(Ar + 4*i); rb[i] = *(const float4*)(Wr + 4*i); }
    const int nit = HID_ >> 5;
    for (int it = 0; it < nit; it++) {
        if (it) __syncthreads();
        #pragma unroll
        for (int i = 0; i < 4; i++) { STS4A2(Ah, Al, lrow, kb + 4*i, ra[i]); STS4B2(Bh, Bl, lrow, kb + 4*i, rb[i]); }
        __syncthreads();
        if (it + 1 < nit) {
            const float* Ap = Ar + (it + 1) * 32;
            const float* Wp = Wr + (it + 1) * 32;
            #pragma unroll
            for (int i = 0; i < 4; i++) { ra[i] = *(const float4*)(Ap + 4*i); rb[i] = *(const float4*)(Wp + 4*i); }
        }
        #pragma unroll
        for (int kt = 0; kt < 4; kt++) {
            uint4 ah[2], al[2]; uint2 bh[4], bl[4];
            #pragma unroll
            for (int mt = 0; mt < 2; mt++) {
                int s = ((wm * 2 + mt) * 4 + kt) * 32 + lane;
                ah[mt] = Ah[s]; al[mt] = Al[s];
            }
            #pragma unroll
            for (int nt = 0; nt < 4; nt++) {
                int s = ((wn * 4 + nt) * 4 + kt) * 32 + lane;
                bh[nt] = Bh[s]; bl[nt] = Bl[s];
            }
            #pragma unroll
            for (int mt = 0; mt < 2; mt++)
                #pragma unroll
                for (int nt = 0; nt < 4; nt++) MMA3(acc[mt][nt], ah[mt], al[mt], bh[nt], bl[nt]);
        }
    }
    const int g = lane >> 2, c2 = (lane & 3) * 2;
    #pragma unroll
    for (int mt = 0; mt < 2; mt++)
        #pragma unroll
        for (int nt = 0; nt < 4; nt++) {
            int r0 = bm + wm * 32 + mt * 16 + g;
            int col = bn + wn * 32 + nt * 8 + c2;
            float4 a = acc[mt][nt];
            if (r0 < cnt) {
                int tok = g_idx[e * NTOK + r0];
                float sc = g_gw[e * NTOK + tok];
                atomicAdd(&g_x[(size_t)tok * D_ + col],     sc * a.x);
                atomicAdd(&g_x[(size_t)tok * D_ + col + 1], sc * a.y);
            }
            if (r0 + 8 < cnt) {
                int tok = g_idx[e * NTOK + r0 + 8];
                float sc = g_gw[e * NTOK + tok];
                atomicAdd(&g_x[(size_t)tok * D_ + col],     sc * a.z);
                atomicAdd(&g_x[(size_t)tok * D_ + col + 1], sc * a.w);
            }
        }
}

// ---------------- embed gather ----------------
__global__ void embed_k(const int* __restrict__ ids, const float* __restrict__ emb) {
    int i = blockIdx.x * 256 + threadIdx.x;
    int n = i >> 8;
    int c = i & 255;
    const float4* src = (const float4*)(emb + (size_t)ids[n] * D_) + c;
    ((float4*)g_x)[i] = *src;
}

// ---------------- rmsnorm ----------------
__global__ void rmsnorm_k(const float* __restrict__ x, const float* __restrict__ w,
                          float* __restrict__ out) {
    int row = blockIdx.x;
    int tid = threadIdx.x;  // 256
    const float* xr = x + (size_t)row * D_;
    float ss = 0.f;
    for (int i = tid; i < D_; i += 256) { float v = xr[i]; ss += v * v; }
    __shared__ float red[256];
    red[tid] = ss; __syncthreads();
    for (int s = 128; s > 0; s >>= 1) {
        if (tid < s) red[tid] += red[tid + s];
        __syncthreads();
    }
    float scale = rsqrtf(red[0] * (1.0f / D_) + 1e-6f);
    for (int i = tid; i < D_; i += 256)
        out[(size_t)row * D_ + i] = xr[i] * scale * w[i];
}

// ---------------- fused attention (one block per (b,h,tq)) ----------------
__global__ void attn_k(const float* __restrict__ q, const float* __restrict__ kk,
                       const float* __restrict__ vv, float* __restrict__ out,
                       int Tk, int causal) {
    int b = blockIdx.z, h = blockIdx.y, tq = blockIdx.x;
    int tid = threadIdx.x;  // 128
    __shared__ float sq[DH];
    __shared__ float sc[TEN];
    __shared__ float red[128];
    const float* qp = q + (size_t)(b * TT + tq) * D_ + h * DH;
    if (tid < DH) sq[tid] = qp[tid];
    __syncthreads();
    int lim = causal ? (tq + 1) : Tk;
    for (int j = tid; j < Tk; j += 128) {
        float s = -1e30f;
        if (j < lim) {
            const float* kp = kk + (size_t)(b * Tk + j) * D_ + h * DH;
            float dot = 0.f;
            #pragma unroll
            for (int d = 0; d < DH; d++) dot += sq[d] * kp[d];
            s = dot * 0.125f;
        }
        sc[j] = s;
    }
    __syncthreads();
    float m = -1e30f;
    for (int j = tid; j < Tk; j += 128) m = fmaxf(m, sc[j]);
    red[tid] = m; __syncthreads();
    for (int s2 = 64; s2 > 0; s2 >>= 1) {
        if (tid < s2) red[tid] = fmaxf(red[tid], red[tid + s2]);
        __syncthreads();
    }
    float mx = red[0];
    __syncthreads();
    float ssum = 0.f;
    for (int j = tid; j < Tk; j += 128) { float e = __expf(sc[j] - mx); sc[j] = e; ssum += e; }
    red[tid] = ssum; __syncthreads();
    for (int s2 = 64; s2 > 0; s2 >>= 1) {
        if (tid < s2) red[tid] += red[tid + s2];
        __syncthreads();
    }
    float inv = 1.0f / red[0];
    __syncthreads();
    if (tid < DH) {
        float o = 0.f;
        for (int j = 0; j < lim; j++)
            o += sc[j] * vv[(size_t)(b * Tk + j) * D_ + h * DH + tid];
        out[(size_t)(b * TT + tq) * D_ + h * DH + tid] = o * inv;
    }
}

// ---------------- router ----------------
__global__ void reset_cnt_k() { if (threadIdx.x < NE) g_cnt[threadIdx.x] = 0; }

__global__ void router_k(const float* __restrict__ xn, const float* __restrict__ rw) {
    int n = blockIdx.x;
    int tid = threadIdx.x;      // 256 = 8 warps = NE experts
    int w = tid >> 5, lane = tid & 31;
    const float* xr = xn + (size_t)n * D_;
    const float* wr = rw + (size_t)w * D_;
    float dot = 0.f;
    for (int i = lane; i < D_; i += 32) dot += xr[i] * wr[i];
    #pragma unroll
    for (int o = 16; o > 0; o >>= 1) dot += __shfl_down_sync(0xffffffffu, dot, o);
    __shared__ float lg[NE];
    if (lane == 0) lg[w] = dot;
    __syncthreads();
    if (tid == 0) {
        int i1 = 0; float v1 = lg[0];
        for (int e = 1; e < NE; e++) if (lg[e] > v1) { v1 = lg[e]; i1 = e; }
        int i2 = -1; float v2 = -1e30f;
        for (int e = 0; e < NE; e++) {
            if (e == i1) continue;
            if (lg[e] > v2) { v2 = lg[e]; i2 = e; }
        }
        float e2 = __expf(v2 - v1);
        float w1 = 1.f / (1.f + e2);
        float w2 = e2 / (1.f + e2);
        g_gw[i1 * NTOK + n] = w1;
        g_gw[i2 * NTOK + n] = w2;
        int p1 = atomicAdd(&g_cnt[i1], 1); g_idx[i1 * NTOK + p1] = n;
        int p2 = atomicAdd(&g_cnt[i2], 1); g_idx[i2 * NTOK + p2] = n;
    }
}

// ---------------- host orchestration ----------------
extern "C" void kernel_launch(void* const* d_in, const int* in_sizes, int n_in,
                              void* d_out, int out_size) {
    const int*   ids  = (const int*)d_in[0];
    const float* enc  = (const float*)d_in[1];
    const float* emb  = (const float*)d_in[2];
    const float* n1   = (const float*)d_in[3];
    const float* n2   = (const float*)d_in[4];
    const float* n3   = (const float*)d_in[5];
    const float* wq_s = (const float*)d_in[6];
    const float* wk_s = (const float*)d_in[7];
    const float* wv_s = (const float*)d_in[8];
    const float* wo_s = (const float*)d_in[9];
    const float* wq_c = (const float*)d_in[10];
    const float* wk_c = (const float*)d_in[11];
    const float* wv_c = (const float*)d_in[12];
    const float* wo_c = (const float*)d_in[13];
    const float* rw   = (const float*)d_in[14];
    const float* wg   = (const float*)d_in[15];
    const float* wu   = (const float*)d_in[16];
    const float* wd   = (const float*)d_in[17];
    const float* fn   = (const float*)d_in[18];
    const float* hw   = (const float*)d_in[19];
    float* out = (float*)d_out;

    float *x, *xn, *q, *k, *v, *ao;
    cudaGetSymbolAddress((void**)&x,  g_x);
    cudaGetSymbolAddress((void**)&xn, g_xn);
    cudaGetSymbolAddress((void**)&q,  g_q);
    cudaGetSymbolAddress((void**)&k,  g_k);
    cudaGetSymbolAddress((void**)&v,  g_v);
    cudaGetSymbolAddress((void**)&ao, g_ao);

    const size_t DD = (size_t)D_ * D_;
    const dim3 gNN(D_ / 64, NTOK / 64);     // 16 x 16
    const dim3 gKV(D_ / 64, NKV / 64);      // 16 x 32

    embed_k<<<NTOK, 256>>>(ids, emb);

    for (int l = 0; l < NL_; l++) {
        // ---- self attention ----
        rmsnorm_k<<<NTOK, 256>>>(x, n1 + l * D_, xn);
        gemm_t<0><<<gNN, 128>>>(xn, wq_s + l * DD, q, NTOK, D_, D_);
        gemm_t<0><<<gNN, 128>>>(xn, wk_s + l * DD, k, NTOK, D_, D_);
        gemm_t<0><<<gNN, 128>>>(xn, wv_s + l * DD, v, NTOK, D_, D_);
        attn_k<<<dim3(TT, H_, BB), 128>>>(q, k, v, ao, TT, 1);
        gemm_t<1><<<gNN, 128>>>(ao, wo_s + l * DD, x, NTOK, D_, D_);

        // ---- cross attention ----
        rmsnorm_k<<<NTOK, 256>>>(x, n2 + l * D_, xn);
        gemm_t<0><<<gNN, 128>>>(xn,  wq_c + l * DD, q, NTOK, D_, D_);
        gemm_t<0><<<gKV, 128>>>(enc, wk_c + l * DD, k, NKV,  D_, D_);
        gemm_t<0><<<gKV, 128>>>(enc, wv_c + l * DD, v, NKV,  D_, D_);
        attn_k<<<dim3(TT, H_, BB), 128>>>(q, k, v, ao, TEN, 0);
        gemm_t<1><<<gNN, 128>>>(ao, wo_c + l * DD, x, NTOK, D_, D_);

        // ---- MoE (gathered, all experts fused per stage) ----
        rmsnorm_k<<<NTOK, 256>>>(x, n3 + l * D_, xn);
        reset_cnt_k<<<1, 32>>>();
        router_k<<<NTOK, 256>>>(xn, rw + (size_t)l * NE * D_);
        moe_gateup_t<<<dim3(HID_ / 64, NTOK / 64, NE), 128>>>(
            xn, wg + (size_t)l * NE * HID_ * D_, wu + (size_t)l * NE * HID_ * D_);
        moe_down_t<<<dim3(D_ / 64, NTOK / 64, NE), 128>>>(
            wd + (size_t)l * NE * D_ * HID_);
    }

    // ---- final norm + heads ----
    rmsnorm_k<<<NTOK, 256>>>(x, fn, xn);
    for (int l = 0; l < LLEV; l++) {
        gemm_t<0><<<dim3(KCB / 64, NTOK / 64), 128>>>(
            xn, hw + (size_t)l * KCB * D_, out + (size_t)l * NTOK * KCB,
            NTOK, KCB, D_);
    }
}

// round 4
// speedup vs baseline: 2.1430x; 1.6827x over previous
#include <cuda_runtime.h>

#define D_    1024
#define H_    16
#define DH    64
#define NL_   2
#define NE    8
#define HID_  4096
#define KCB   8192
#define LLEV  3
#define BB    8
#define TT    128
#define TEN   256
#define NTOK  (BB*TT)    /* 1024 */
#define NKV   (BB*TEN)   /* 2048 */

// ---------------- scratch ----------------
__device__ float g_x [NTOK*D_];
__device__ float g_xn[NTOK*D_];
__device__ float g_q [NTOK*D_];
__device__ float g_k [NKV*D_];
__device__ float g_v [NKV*D_];
__device__ float g_ao[NTOK*D_];
__device__ float g_h2[(size_t)NE*NTOK*HID_];
__device__ float g_gw[NE*NTOK];
__device__ int   g_cnt[NE];
__device__ int   g_idx[NE*NTOK];

// ---------------- helpers ----------------
__device__ __forceinline__ unsigned f2tf(float x) {
    unsigned u; asm("cvt.rna.tf32.f32 %0, %1;" : "=r"(u) : "f"(x)); return u;
}
__device__ __forceinline__ void sp(float v, unsigned& h, unsigned& l) {
    h = f2tf(v); l = f2tf(v - __uint_as_float(h));
}
__device__ __forceinline__ void mma8(float4& d, const uint4& a, const uint2& b) {
    asm volatile("mma.sync.aligned.m16n8k8.row.col.f32.tf32.tf32.f32 "
                 "{%0,%1,%2,%3}, {%4,%5,%6,%7}, {%8,%9}, {%0,%1,%2,%3};"
                 : "+f"(d.x), "+f"(d.y), "+f"(d.z), "+f"(d.w)
                 : "r"(a.x), "r"(a.y), "r"(a.z), "r"(a.w), "r"(b.x), "r"(b.y));
}
#define MMA3(acc, ah, al, bh, bl) do { mma8(acc, ah, bh); mma8(acc, al, bh); mma8(acc, ah, bl); } while(0)

__device__ __forceinline__ void cpa16(float* smem_dst, const float* gsrc) {
    unsigned s = (unsigned)__cvta_generic_to_shared(smem_dst);
    asm volatile("cp.async.cg.shared.global [%0], [%1], 16;" :: "r"(s), "l"(gsrc));
}
#define CP_COMMIT() asm volatile("cp.async.commit_group;")
#define CP_WAIT1()  asm volatile("cp.async.wait_group 1;")
#define CP_WAIT0()  asm volatile("cp.async.wait_group 0;")

// swizzled float index within a (rows x 32) tile
__device__ __forceinline__ int swz(int row, int col) { return row * 32 + (col ^ ((row & 7) << 2)); }

// ---------------- generic split-tf32 GEMM: C[M,N] = A[M,K]*W[N,K]^T (+C) ----------------
// 128x64x32 tiles, 256 threads (8 warps; warp tile 32x32). M mult 128, N mult 64, K mult 64.
template <int ADD>
__global__ __launch_bounds__(256, 2)
void gemm_t(const float* __restrict__ A, const float* __restrict__ W,
            float* __restrict__ C, int M, int N, int K) {
    __shared__ float As[2][128 * 32];
    __shared__ float Bs[2][64 * 32];
    const int bm = blockIdx.y * 128, bn = blockIdx.x * 64;
    const int tid = threadIdx.x, lane = tid & 31, warp = tid >> 5;
    const int wm = warp >> 1, wn = warp & 1;
    const int lrow = tid >> 3, lc4 = (tid & 7) << 2;

    float4 acc[2][4];
    #pragma unroll
    for (int i = 0; i < 2; i++)
        #pragma unroll
        for (int j = 0; j < 4; j++) acc[i][j] = make_float4(0.f, 0.f, 0.f, 0.f);

    auto load_stage = [&](int buf, int k0) {
        #pragma unroll
        for (int i = 0; i < 4; i++) {
            int row = lrow + i * 32;
            cpa16(&As[buf][swz(row, lc4)], A + (size_t)(bm + row) * K + k0 + lc4);
        }
        #pragma unroll
        for (int i = 0; i < 2; i++) {
            int row = lrow + i * 32;
            cpa16(&Bs[buf][swz(row, lc4)], W + (size_t)(bn + row) * K + k0 + lc4);
        }
    };

    const int nit = K >> 5;
    load_stage(0, 0); CP_COMMIT();
    load_stage(1, 32); CP_COMMIT();
    CP_WAIT1();
    __syncthreads();

    const int sw = (lane >> 2) << 2;
    const int g4 = lane >> 2, l4 = lane & 3;

    for (int it = 0; it < nit; it++) {
        const int buf = it & 1;
        #pragma unroll
        for (int kt = 0; kt < 4; kt++) {
            const int c0 = (kt * 8 + l4) ^ sw;
            const int c1 = (kt * 8 + 4 + l4) ^ sw;
            uint4 ah[2], al[2];
            #pragma unroll
            for (int mt = 0; mt < 2; mt++) {
                int r0 = (wm * 32 + mt * 16 + g4) * 32;
                int r1 = r0 + 8 * 32;
                float f0 = As[buf][r0 + c0], f1 = As[buf][r1 + c0];
                float f2 = As[buf][r0 + c1], f3 = As[buf][r1 + c1];
                sp(f0, ah[mt].x, al[mt].x); sp(f1, ah[mt].y, al[mt].y);
                sp(f2, ah[mt].z, al[mt].z); sp(f3, ah[mt].w, al[mt].w);
            }
            #pragma unroll
            for (int nt = 0; nt < 4; nt++) {
                int n0 = (wn * 32 + nt * 8 + g4) * 32;
                float f0 = Bs[buf][n0 + c0], f1 = Bs[buf][n0 + c1];
                uint2 bh, bl;
                sp(f0, bh.x, bl.x); sp(f1, bh.y, bl.y);
                #pragma unroll
                for (int mt = 0; mt < 2; mt++) MMA3(acc[mt][nt], ah[mt], al[mt], bh, bl);
            }
        }
        __syncthreads();
        if (it + 2 < nit) { load_stage(buf, (it + 2) * 32); CP_COMMIT(); CP_WAIT1(); }
        else CP_WAIT0();
        __syncthreads();
    }

    const int c2 = l4 * 2;
    #pragma unroll
    for (int mt = 0; mt < 2; mt++)
        #pragma unroll
        for (int nt = 0; nt < 4; nt++) {
            int row = bm + wm * 32 + mt * 16 + g4;
            int col = bn + wn * 32 + nt * 8 + c2;
            float* p0 = C + (size_t)row * N + col;
            float* p1 = C + (size_t)(row + 8) * N + col;
            float4 a = acc[mt][nt];
            if (ADD) { p0[0] += a.x; p0[1] += a.y; p1[0] += a.z; p1[1] += a.w; }
            else { *(float2*)p0 = make_float2(a.x, a.y); *(float2*)p1 = make_float2(a.z, a.w); }
        }
}

// ---------------- MoE gate+up fused (gathered, all experts) ----------------
// 64x64x32 tiles, 256 threads (8 warps; warp tile 16x32).
__global__ __launch_bounds__(256, 2)
void moe_gateup_t(const float* __restrict__ xn, const float* __restrict__ wg,
                  const float* __restrict__ wu) {
    const int e = blockIdx.z;
    const int cnt = g_cnt[e];
    const int bm = blockIdx.y * 64;
    if (bm >= cnt) return;
    const int bn = blockIdx.x * 64;
    __shared__ float As[2][64 * 32];
    __shared__ float Gs[2][64 * 32];
    __shared__ float Us[2][64 * 32];
    const int tid = threadIdx.x, lane = tid & 31, warp = tid >> 5;
    const int wm = warp >> 1, wn = warp & 1;
    const int lrow = tid >> 3, lc4 = (tid & 7) << 2;

    int tok0, tok1;
    {
        int r0 = bm + lrow;      tok0 = g_idx[e * NTOK + (r0 < cnt ? r0 : cnt - 1)];
        int r1 = bm + lrow + 32; tok1 = g_idx[e * NTOK + (r1 < cnt ? r1 : cnt - 1)];
    }
    const float* Gb = wg + (size_t)e * HID_ * D_;
    const float* Ub = wu + (size_t)e * HID_ * D_;

    float4 ag[4], au[4];
    #pragma unroll
    for (int j = 0; j < 4; j++) { ag[j] = make_float4(0.f,0.f,0.f,0.f); au[j] = make_float4(0.f,0.f,0.f,0.f); }

    auto load_stage = [&](int buf, int k0) {
        cpa16(&As[buf][swz(lrow, lc4)],      xn + (size_t)tok0 * D_ + k0 + lc4);
        cpa16(&As[buf][swz(lrow + 32, lc4)], xn + (size_t)tok1 * D_ + k0 + lc4);
        #pragma unroll
        for (int i = 0; i < 2; i++) {
            int row = lrow + i * 32;
            cpa16(&Gs[buf][swz(row, lc4)], Gb + (size_t)(bn + row) * D_ + k0 + lc4);
            cpa16(&Us[buf][swz(row, lc4)], Ub + (size_t)(bn + row) * D_ + k0 + lc4);
        }
    };

    const int nit = D_ >> 5;
    load_stage(0, 0); CP_COMMIT();
    load_stage(1, 32); CP_COMMIT();
    CP_WAIT1();
    __syncthreads();

    const int sw = (lane >> 2) << 2;
    const int g4 = lane >> 2, l4 = lane & 3;

    for (int it = 0; it < nit; it++) {
        const int buf = it & 1;
        #pragma unroll
        for (int kt = 0; kt < 4; kt++) {
            const int c0 = (kt * 8 + l4) ^ sw;
            const int c1 = (kt * 8 + 4 + l4) ^ sw;
            uint4 ah, al;
            {
                int r0 = (wm * 16 + g4) * 32;
                int r1 = r0 + 8 * 32;
                float f0 = As[buf][r0 + c0], f1 = As[buf][r1 + c0];
                float f2 = As[buf][r0 + c1], f3 = As[buf][r1 + c1];
                sp(f0, ah.x, al.x); sp(f1, ah.y, al.y); sp(f2, ah.z, al.z); sp(f3, ah.w, al.w);
            }
            #pragma unroll
            for (int nt = 0; nt < 4; nt++) {
                int n0 = (wn * 32 + nt * 8 + g4) * 32;
                float g0 = Gs[buf][n0 + c0], g1 = Gs[buf][n0 + c1];
                float u0 = Us[buf][n0 + c0], u1 = Us[buf][n0 + c1];
                uint2 gh, gl, uh, ul;
                sp(g0, gh.x, gl.x); sp(g1, gh.y, gl.y);
                sp(u0, uh.x, ul.x); sp(u1, uh.y, ul.y);
                MMA3(ag[nt], ah, al, gh, gl);
                MMA3(au[nt], ah, al, uh, ul);
            }
        }
        __syncthreads();
        if (it + 2 < nit) { load_stage(buf, (it + 2) * 32); CP_COMMIT(); CP_WAIT1(); }
        else CP_WAIT0();
        __syncthreads();
    }

    const int c2 = l4 * 2;
    float* hb = g_h2 + (size_t)e * NTOK * HID_;
    #pragma unroll
    for (int nt = 0; nt < 4; nt++) {
        int r0 = bm + wm * 16 + g4;
        int col = bn + wn * 32 + nt * 8 + c2;
        float4 gg = ag[nt], uu = au[nt];
        if (r0 < cnt) {
            float s0 = gg.x / (1.f + __expf(-gg.x));
            float s1 = gg.y / (1.f + __expf(-gg.y));
            *(float2*)(hb + (size_t)r0 * HID_ + col) = make_float2(s0 * uu.x, s1 * uu.y);
        }
        if (r0 + 8 < cnt) {
            float s2 = gg.z / (1.f + __expf(-gg.z));
            float s3 = gg.w / (1.f + __expf(-gg.w));
            *(float2*)(hb + (size_t)(r0 + 8) * HID_ + col) = make_float2(s2 * uu.z, s3 * uu.w);
        }
    }
}

// ---------------- MoE down (scatter-add into residual) ----------------
// 128x64x32 tiles, 256 threads.
__global__ __launch_bounds__(256, 2)
void moe_down_t(const float* __restrict__ wd) {
    const int e = blockIdx.z;
    const int cnt = g_cnt[e];
    const int bm = blockIdx.y * 128;
    if (bm >= cnt) return;
    const int bn = blockIdx.x * 64;
    __shared__ float As[2][128 * 32];
    __shared__ float Bs[2][64 * 32];
    const int tid = threadIdx.x, lane = tid & 31, warp = tid >> 5;
    const int wm = warp >> 1, wn = warp & 1;
    const int lrow = tid >> 3, lc4 = (tid & 7) << 2;

    const float* Ab = g_h2 + ((size_t)e * NTOK + bm) * HID_;
    const float* Bb = wd + (size_t)e * D_ * HID_;

    float4 acc[2][4];
    #pragma unroll
    for (int i = 0; i < 2; i++)
        #pragma unroll
        for (int j = 0; j < 4; j++) acc[i][j] = make_float4(0.f, 0.f, 0.f, 0.f);

    auto load_stage = [&](int buf, int k0) {
        #pragma unroll
        for (int i = 0; i < 4; i++) {
            int row = lrow + i * 32;
            cpa16(&As[buf][swz(row, lc4)], Ab + (size_t)row * HID_ + k0 + lc4);
        }
        #pragma unroll
        for (int i = 0; i < 2; i++) {
            int row = lrow + i * 32;
            cpa16(&Bs[buf][swz(row, lc4)], Bb + (size_t)(bn + row) * HID_ + k0 + lc4);
        }
    };

    const int nit = HID_ >> 5;
    load_stage(0, 0); CP_COMMIT();
    load_stage(1, 32); CP_COMMIT();
    CP_WAIT1();
    __syncthreads();

    const int sw = (lane >> 2) << 2;
    const int g4 = lane >> 2, l4 = lane & 3;

    for (int it = 0; it < nit; it++) {
        const int buf = it & 1;
        #pragma unroll
        for (int kt = 0; kt < 4; kt++) {
            const int c0 = (kt * 8 + l4) ^ sw;
            const int c1 = (kt * 8 + 4 + l4) ^ sw;
            uint4 ah[2], al[2];
            #pragma unroll
            for (int mt = 0; mt < 2; mt++) {
                int r0 = (wm * 32 + mt * 16 + g4) * 32;
                int r1 = r0 + 8 * 32;
                float f0 = As[buf][r0 + c0], f1 = As[buf][r1 + c0];
                float f2 = As[buf][r0 + c1], f3 = As[buf][r1 + c1];
                sp(f0, ah[mt].x, al[mt].x); sp(f1, ah[mt].y, al[mt].y);
                sp(f2, ah[mt].z, al[mt].z); sp(f3, ah[mt].w, al[mt].w);
            }
            #pragma unroll
            for (int nt = 0; nt < 4; nt++) {
                int n0 = (wn * 32 + nt * 8 + g4) * 32;
                float f0 = Bs[buf][n0 + c0], f1 = Bs[buf][n0 + c1];
                uint2 bh, bl;
                sp(f0, bh.x, bl.x); sp(f1, bh.y, bl.y);
                #pragma unroll
                for (int mt = 0; mt < 2; mt++) MMA3(acc[mt][nt], ah[mt], al[mt], bh, bl);
            }
        }
        __syncthreads();
        if (it + 2 < nit) { load_stage(buf, (it + 2) * 32); CP_COMMIT(); CP_WAIT1(); }
        else CP_WAIT0();
        __syncthreads();
    }

    const int c2 = l4 * 2;
    #pragma unroll
    for (int mt = 0; mt < 2; mt++)
        #pragma unroll
        for (int nt = 0; nt < 4; nt++) {
            int r0 = bm + wm * 32 + mt * 16 + g4;
            int col = bn + wn * 32 + nt * 8 + c2;
            float4 a = acc[mt][nt];
            if (r0 < cnt) {
                int tok = g_idx[e * NTOK + r0];
                float sc = g_gw[e * NTOK + tok];
                atomicAdd(&g_x[(size_t)tok * D_ + col],     sc * a.x);
                atomicAdd(&g_x[(size_t)tok * D_ + col + 1], sc * a.y);
            }
            if (r0 + 8 < cnt) {
                int tok = g_idx[e * NTOK + r0 + 8];
                float sc = g_gw[e * NTOK + tok];
                atomicAdd(&g_x[(size_t)tok * D_ + col],     sc * a.z);
                atomicAdd(&g_x[(size_t)tok * D_ + col + 1], sc * a.w);
            }
        }
}

// ---------------- embed gather ----------------
__global__ void embed_k(const int* __restrict__ ids, const float* __restrict__ emb) {
    int i = blockIdx.x * 256 + threadIdx.x;
    int n = i >> 8;
    int c = i & 255;
    const float4* src = (const float4*)(emb + (size_t)ids[n] * D_) + c;
    ((float4*)g_x)[i] = *src;
}

// ---------------- rmsnorm ----------------
__global__ void rmsnorm_k(const float* __restrict__ x, const float* __restrict__ w,
                          float* __restrict__ out) {
    int row = blockIdx.x;
    int tid = threadIdx.x;  // 256
    const float* xr = x + (size_t)row * D_;
    float ss = 0.f;
    for (int i = tid; i < D_; i += 256) { float v = xr[i]; ss += v * v; }
    __shared__ float red[256];
    red[tid] = ss; __syncthreads();
    for (int s = 128; s > 0; s >>= 1) {
        if (tid < s) red[tid] += red[tid + s];
        __syncthreads();
    }
    float scale = rsqrtf(red[0] * (1.0f / D_) + 1e-6f);
    for (int i = tid; i < D_; i += 256)
        out[(size_t)row * D_ + i] = xr[i] * scale * w[i];
}

// ---------------- fused attention ----------------
__global__ void attn_k(const float* __restrict__ q, const float* __restrict__ kk,
                       const float* __restrict__ vv, float* __restrict__ out,
                       int Tk, int causal) {
    int b = blockIdx.z, h = blockIdx.y, tq = blockIdx.x;
    int tid = threadIdx.x;  // 128
    __shared__ float sq[DH];
    __shared__ float sc[TEN];
    __shared__ float red[128];
    const float* qp = q + (size_t)(b * TT + tq) * D_ + h * DH;
    if (tid < DH) sq[tid] = qp[tid];
    __syncthreads();
    int lim = causal ? (tq + 1) : Tk;
    for (int j = tid; j < Tk; j += 128) {
        float s = -1e30f;
        if (j < lim) {
            const float* kp = kk + (size_t)(b * Tk + j) * D_ + h * DH;
            float dot = 0.f;
            #pragma unroll
            for (int d = 0; d < DH; d++) dot += sq[d] * kp[d];
            s = dot * 0.125f;
        }
        sc[j] = s;
    }
    __syncthreads();
    float m = -1e30f;
    for (int j = tid; j < Tk; j += 128) m = fmaxf(m, sc[j]);
    red[tid] = m; __syncthreads();
    for (int s2 = 64; s2 > 0; s2 >>= 1) {
        if (tid < s2) red[tid] = fmaxf(red[tid], red[tid + s2]);
        __syncthreads();
    }
    float mx = red[0];
    __syncthreads();
    float ssum = 0.f;
    for (int j = tid; j < Tk; j += 128) { float e = __expf(sc[j] - mx); sc[j] = e; ssum += e; }
    red[tid] = ssum; __syncthreads();
    for (int s2 = 64; s2 > 0; s2 >>= 1) {
        if (tid < s2) red[tid] += red[tid + s2];
        __syncthreads();
    }
    float inv = 1.0f / red[0];
    __syncthreads();
    if (tid < DH) {
        float o = 0.f;
        for (int j = 0; j < lim; j++)
            o += sc[j] * vv[(size_t)(b * Tk + j) * D_ + h * DH + tid];
        out[(size_t)(b * TT + tq) * D_ + h * DH + tid] = o * inv;
    }
}

// ---------------- router ----------------
__global__ void reset_cnt_k() { if (threadIdx.x < NE) g_cnt[threadIdx.x] = 0; }

__global__ void router_k(const float* __restrict__ xn, const float* __restrict__ rw) {
    int n = blockIdx.x;
    int tid = threadIdx.x;      // 256 = 8 warps = NE experts
    int w = tid >> 5, lane = tid & 31;
    const float* xr = xn + (size_t)n * D_;
    const float* wr = rw + (size_t)w * D_;
    float dot = 0.f;
    for (int i = lane; i < D_; i += 32) dot += xr[i] * wr[i];
    #pragma unroll
    for (int o = 16; o > 0; o >>= 1) dot += __shfl_down_sync(0xffffffffu, dot, o);
    __shared__ float lg[NE];
    if (lane == 0) lg[w] = dot;
    __syncthreads();
    if (tid == 0) {
        int i1 = 0; float v1 = lg[0];
        for (int e = 1; e < NE; e++) if (lg[e] > v1) { v1 = lg[e]; i1 = e; }
        int i2 = -1; float v2 = -1e30f;
        for (int e = 0; e < NE; e++) {
            if (e == i1) continue;
            if (lg[e] > v2) { v2 = lg[e]; i2 = e; }
        }
        float e2 = __expf(v2 - v1);
        float w1 = 1.f / (1.f + e2);
        float w2 = e2 / (1.f + e2);
        g_gw[i1 * NTOK + n] = w1;
        g_gw[i2 * NTOK + n] = w2;
        int p1 = atomicAdd(&g_cnt[i1], 1); g_idx[i1 * NTOK + p1] = n;
        int p2 = atomicAdd(&g_cnt[i2], 1); g_idx[i2 * NTOK + p2] = n;
    }
}

// ---------------- host orchestration ----------------
extern "C" void kernel_launch(void* const* d_in, const int* in_sizes, int n_in,
                              void* d_out, int out_size) {
    const int*   ids  = (const int*)d_in[0];
    const float* enc  = (const float*)d_in[1];
    const float* emb  = (const float*)d_in[2];
    const float* n1   = (const float*)d_in[3];
    const float* n2   = (const float*)d_in[4];
    const float* n3   = (const float*)d_in[5];
    const float* wq_s = (const float*)d_in[6];
    const float* wk_s = (const float*)d_in[7];
    const float* wv_s = (const float*)d_in[8];
    const float* wo_s = (const float*)d_in[9];
    const float* wq_c = (const float*)d_in[10];
    const float* wk_c = (const float*)d_in[11];
    const float* wv_c = (const float*)d_in[12];
    const float* wo_c = (const float*)d_in[13];
    const float* rw   = (const float*)d_in[14];
    const float* wg   = (const float*)d_in[15];
    const float* wu   = (const float*)d_in[16];
    const float* wd   = (const float*)d_in[17];
    const float* fn   = (const float*)d_in[18];
    const float* hw   = (const float*)d_in[19];
    float* out = (float*)d_out;

    float *x, *xn, *q, *k, *v, *ao;
    cudaGetSymbolAddress((void**)&x,  g_x);
    cudaGetSymbolAddress((void**)&xn, g_xn);
    cudaGetSymbolAddress((void**)&q,  g_q);
    cudaGetSymbolAddress((void**)&k,  g_k);
    cudaGetSymbolAddress((void**)&v,  g_v);
    cudaGetSymbolAddress((void**)&ao, g_ao);

    const size_t DD = (size_t)D_ * D_;
    const dim3 gNN(D_ / 64, NTOK / 128);    // 16 x 8
    const dim3 gKV(D_ / 64, NKV / 128);     // 16 x 16

    embed_k<<<NTOK, 256>>>(ids, emb);

    for (int l = 0; l < NL_; l++) {
        // ---- self attention ----
        rmsnorm_k<<<NTOK, 256>>>(x, n1 + l * D_, xn);
        gemm_t<0><<<gNN, 256>>>(xn, wq_s + l * DD, q, NTOK, D_, D_);
        gemm_t<0><<<gNN, 256>>>(xn, wk_s + l * DD, k, NTOK, D_, D_);
        gemm_t<0><<<gNN, 256>>>(xn, wv_s + l * DD, v, NTOK, D_, D_);
        attn_k<<<dim3(TT, H_, BB), 128>>>(q, k, v, ao, TT, 1);
        gemm_t<1><<<gNN, 256>>>(ao, wo_s + l * DD, x, NTOK, D_, D_);

        // ---- cross attention ----
        rmsnorm_k<<<NTOK, 256>>>(x, n2 + l * D_, xn);
        gemm_t<0><<<gNN, 256>>>(xn,  wq_c + l * DD, q, NTOK, D_, D_);
        gemm_t<0><<<gKV, 256>>>(enc, wk_c + l * DD, k, NKV,  D_, D_);
        gemm_t<0><<<gKV, 256>>>(enc, wv_c + l * DD, v, NKV,  D_, D_);
        attn_k<<<dim3(TT, H_, BB), 128>>>(q, k, v, ao, TEN, 0);
        gemm_t<1><<<gNN, 256>>>(ao, wo_c + l * DD, x, NTOK, D_, D_);

        // ---- MoE ----
        rmsnorm_k<<<NTOK, 256>>>(x, n3 + l * D_, xn);
        reset_cnt_k<<<1, 32>>>();
        router_k<<<NTOK, 256>>>(xn, rw + (size_t)l * NE * D_);
        moe_gateup_t<<<dim3(HID_ / 64, NTOK / 64, NE), 256>>>(
            xn, wg + (size_t)l * NE * HID_ * D_, wu + (size_t)l * NE * HID_ * D_);
        moe_down_t<<<dim3(D_ / 64, NTOK / 128, NE), 256>>>(
            wd + (size_t)l * NE * D_ * HID_);
    }

    // ---- final norm + heads ----
    rmsnorm_k<<<NTOK, 256>>>(x, fn, xn);
    for (int l = 0; l < LLEV; l++) {
        gemm_t<0><<<dim3(KCB / 64, NTOK / 128), 256>>>(
            xn, hw + (size_t)l * KCB * D_, out + (size_t)l * NTOK * KCB,
            NTOK, KCB, D_);
    }
}

// round 5
// speedup vs baseline: 2.9616x; 1.3820x over previous
#include <cuda_runtime.h>

#define D_    1024
#define H_    16
#define DH    64
#define NL_   2
#define NE    8
#define HID_  4096
#define KCB   8192
#define LLEV  3
#define BB    8
#define TT    128
#define TEN   256
#define NTOK  (BB*TT)    /* 1024 */
#define NKV   (BB*TEN)   /* 2048 */

// ---------------- scratch ----------------
__device__ float g_x [NTOK*D_];
__device__ float g_xn[NTOK*D_];
__device__ float g_q [NTOK*D_];
__device__ float g_k [NKV*D_];
__device__ float g_v [NKV*D_];
__device__ float g_ao[NTOK*D_];
__device__ float g_h2[(size_t)NE*NTOK*HID_];
__device__ float g_gw[NE*NTOK];
__device__ int   g_cnt[NE];
__device__ int   g_idx[NE*NTOK];

// ---------------- bf16x3 helpers ----------------
__device__ __forceinline__ void cvt2(float2 v, unsigned& h, unsigned& m) {
    unsigned hp;
    asm("cvt.rn.bf16x2.f32 %0, %1, %2;" : "=r"(hp) : "f"(v.y), "f"(v.x));
    float r0 = v.x - __uint_as_float(hp << 16);
    float r1 = v.y - __uint_as_float(hp & 0xffff0000u);
    asm("cvt.rn.bf16x2.f32 %0, %1, %2;" : "=r"(m) : "f"(r1), "f"(r0));
    h = hp;
}
__device__ __forceinline__ void mmab(float4& d, const uint4& a, const uint2& b) {
    asm volatile("mma.sync.aligned.m16n8k16.row.col.f32.bf16.bf16.f32 "
                 "{%0,%1,%2,%3}, {%4,%5,%6,%7}, {%8,%9}, {%0,%1,%2,%3};"
                 : "+f"(d.x), "+f"(d.y), "+f"(d.z), "+f"(d.w)
                 : "r"(a.x), "r"(a.y), "r"(a.z), "r"(a.w), "r"(b.x), "r"(b.y));
}
// 3-term: h*h + m*h + h*m  (dropped ~2^-17)
#define MMA3B(acc, ah, am, bh, bm) do { mmab(acc, ah, bh); mmab(acc, am, bh); mmab(acc, ah, bm); } while(0)

__device__ __forceinline__ void cpa16(float* smem_dst, const float* gsrc) {
    unsigned s = (unsigned)__cvta_generic_to_shared(smem_dst);
    asm volatile("cp.async.cg.shared.global [%0], [%1], 16;" :: "r"(s), "l"(gsrc));
}
#define CP_COMMIT() asm volatile("cp.async.commit_group;")
#define CP_WAIT1()  asm volatile("cp.async.wait_group 1;")
#define CP_WAIT0()  asm volatile("cp.async.wait_group 0;")

// swizzled float index within a (rows x 32) tile: conflict-free for float4 row
// stores and float2 fragment loads (4 rows/phase -> 4 disjoint 8-col groups)
__device__ __forceinline__ int swz(int row, int col) { return row * 32 + (col ^ ((row & 3) << 3)); }
__device__ __forceinline__ float2 ld2s(const float* S, int row, int c) {
    return *(const float2*)(S + row * 32 + (c ^ ((row & 3) << 3)));
}

// A fragment (m16 rows base rbase) for k16 chunk at kc; packed bf16 h/m
__device__ __forceinline__ void fragA(const float* S, int rbase, int g4, int kc,
                                      uint4& ah, uint4& am) {
    float2 p0 = ld2s(S, rbase + g4, kc);
    float2 p1 = ld2s(S, rbase + g4 + 8, kc);
    float2 p2 = ld2s(S, rbase + g4, kc + 8);
    float2 p3 = ld2s(S, rbase + g4 + 8, kc + 8);
    cvt2(p0, ah.x, am.x); cvt2(p1, ah.y, am.y); cvt2(p2, ah.z, am.z); cvt2(p3, ah.w, am.w);
}
__device__ __forceinline__ void fragB(const float* S, int n, int kc, uint2& bh, uint2& bm) {
    float2 q0 = ld2s(S, n, kc);
    float2 q1 = ld2s(S, n, kc + 8);
    cvt2(q0, bh.x, bm.x); cvt2(q1, bh.y, bm.y);
}

// ---------------- GEMM body: C[M,N] = A[M,K]*W[N,K]^T (+C) ----------------
// 128x64x32 tiles, 256 threads (8 warps; warp tile 32x32). M mult 128, N mult 64, K mult 64.
template <int ADD>
__device__ __forceinline__
void gemm_body(const float* __restrict__ A, const float* __restrict__ W,
               float* __restrict__ C, int bm, int bn, int N, int K,
               float (*As)[128 * 32], float (*Bs)[64 * 32]) {
    const int tid = threadIdx.x, lane = tid & 31, warp = tid >> 5;
    const int wm = warp >> 1, wn = warp & 1;
    const int lrow = tid >> 3, lc4 = (tid & 7) << 2;
    const int g4 = lane >> 2, l4 = lane & 3;

    float4 acc[2][4];
    #pragma unroll
    for (int i = 0; i < 2; i++)
        #pragma unroll
        for (int j = 0; j < 4; j++) acc[i][j] = make_float4(0.f, 0.f, 0.f, 0.f);

    auto load_stage = [&](int buf, int k0) {
        #pragma unroll
        for (int i = 0; i < 4; i++) {
            int row = lrow + i * 32;
            cpa16(&As[buf][swz(row, lc4)], A + (size_t)(bm + row) * K + k0 + lc4);
        }
        #pragma unroll
        for (int i = 0; i < 2; i++) {
            int row = lrow + i * 32;
            cpa16(&Bs[buf][swz(row, lc4)], W + (size_t)(bn + row) * K + k0 + lc4);
        }
    };

    const int nit = K >> 5;
    load_stage(0, 0); CP_COMMIT();
    load_stage(1, 32); CP_COMMIT();
    CP_WAIT1();
    __syncthreads();

    for (int it = 0; it < nit; it++) {
        const int buf = it & 1;
        #pragma unroll
        for (int kt2 = 0; kt2 < 2; kt2++) {
            const int kc = kt2 * 16 + l4 * 2;
            uint4 ah[2], am[2];
            #pragma unroll
            for (int mt = 0; mt < 2; mt++) fragA(As[buf], wm * 32 + mt * 16, g4, kc, ah[mt], am[mt]);
            #pragma unroll
            for (int nt = 0; nt < 4; nt++) {
                uint2 bh, bmm;
                fragB(Bs[buf], wn * 32 + nt * 8 + g4, kc, bh, bmm);
                #pragma unroll
                for (int mt = 0; mt < 2; mt++) MMA3B(acc[mt][nt], ah[mt], am[mt], bh, bmm);
            }
        }
        __syncthreads();
        if (it + 2 < nit) { load_stage(buf, (it + 2) * 32); CP_COMMIT(); CP_WAIT1(); }
        else CP_WAIT0();
        __syncthreads();
    }

    const int c2 = l4 * 2;
    #pragma unroll
    for (int mt = 0; mt < 2; mt++)
        #pragma unroll
        for (int nt = 0; nt < 4; nt++) {
            int row = bm + wm * 32 + mt * 16 + g4;
            int col = bn + wn * 32 + nt * 8 + c2;
            float* p0 = C + (size_t)row * N + col;
            float* p1 = C + (size_t)(row + 8) * N + col;
            float4 a = acc[mt][nt];
            if (ADD) { p0[0] += a.x; p0[1] += a.y; p1[0] += a.z; p1[1] += a.w; }
            else { *(float2*)p0 = make_float2(a.x, a.y); *(float2*)p1 = make_float2(a.z, a.w); }
        }
}

template <int ADD>
__global__ __launch_bounds__(256, 2)
void gemm_t(const float* __restrict__ A, const float* __restrict__ W,
            float* __restrict__ C, int M, int N, int K) {
    __shared__ float As[2][128 * 32];
    __shared__ float Bs[2][64 * 32];
    gemm_body<ADD>(A, W, C, blockIdx.y * 128, blockIdx.x * 64, N, K, As, Bs);
}

// z-fused variant: 3 weight/output pairs selected by blockIdx.z
template <int ADD>
__global__ __launch_bounds__(256, 2)
void gemm_t3(const float* __restrict__ A,
             const float* __restrict__ W0, const float* __restrict__ W1, const float* __restrict__ W2,
             float* __restrict__ C0, float* __restrict__ C1, float* __restrict__ C2,
             int M, int N, int K) {
    __shared__ float As[2][128 * 32];
    __shared__ float Bs[2][64 * 32];
    const float* W = blockIdx.z == 0 ? W0 : (blockIdx.z == 1 ? W1 : W2);
    float* C = blockIdx.z == 0 ? C0 : (blockIdx.z == 1 ? C1 : C2);
    gemm_body<ADD>(A, W, C, blockIdx.y * 128, blockIdx.x * 64, N, K, As, Bs);
}

// ---------------- MoE gate+up fused (gathered, all experts) ----------------
// 64x64x32 tiles, 256 threads (8 warps; warp tile 16x32).
__global__ __launch_bounds__(256, 2)
void moe_gateup_t(const float* __restrict__ xn, const float* __restrict__ wg,
                  const float* __restrict__ wu) {
    const int e = blockIdx.z;
    const int cnt = g_cnt[e];
    const int bm = blockIdx.y * 64;
    if (bm >= cnt) return;
    const int bn = blockIdx.x * 64;
    __shared__ float As[2][64 * 32];
    __shared__ float Gs[2][64 * 32];
    __shared__ float Us[2][64 * 32];
    const int tid = threadIdx.x, lane = tid & 31, warp = tid >> 5;
    const int wm = warp >> 1, wn = warp & 1;
    const int lrow = tid >> 3, lc4 = (tid & 7) << 2;
    const int g4 = lane >> 2, l4 = lane & 3;

    int tok0, tok1;
    {
        int r0 = bm + lrow;      tok0 = g_idx[e * NTOK + (r0 < cnt ? r0 : cnt - 1)];
        int r1 = bm + lrow + 32; tok1 = g_idx[e * NTOK + (r1 < cnt ? r1 : cnt - 1)];
    }
    const float* Gb = wg + (size_t)e * HID_ * D_;
    const float* Ub = wu + (size_t)e * HID_ * D_;

    float4 ag[4], au[4];
    #pragma unroll
    for (int j = 0; j < 4; j++) { ag[j] = make_float4(0.f,0.f,0.f,0.f); au[j] = make_float4(0.f,0.f,0.f,0.f); }

    auto load_stage = [&](int buf, int k0) {
        cpa16(&As[buf][swz(lrow, lc4)],      xn + (size_t)tok0 * D_ + k0 + lc4);
        cpa16(&As[buf][swz(lrow + 32, lc4)], xn + (size_t)tok1 * D_ + k0 + lc4);
        #pragma unroll
        for (int i = 0; i < 2; i++) {
            int row = lrow + i * 32;
            cpa16(&Gs[buf][swz(row, lc4)], Gb + (size_t)(bn + row) * D_ + k0 + lc4);
            cpa16(&Us[buf][swz(row, lc4)], Ub + (size_t)(bn + row) * D_ + k0 + lc4);
        }
    };

    const int nit = D_ >> 5;
    load_stage(0, 0); CP_COMMIT();
    load_stage(1, 32); CP_COMMIT();
    CP_WAIT1();
    __syncthreads();

    for (int it = 0; it < nit; it++) {
        const int buf = it & 1;
        #pragma unroll
        for (int kt2 = 0; kt2 < 2; kt2++) {
            const int kc = kt2 * 16 + l4 * 2;
            uint4 ah, am;
            fragA(As[buf], wm * 16, g4, kc, ah, am);
            #pragma unroll
            for (int nt = 0; nt < 4; nt++) {
                int n = wn * 32 + nt * 8 + g4;
                uint2 gh, gm, uh, um;
                fragB(Gs[buf], n, kc, gh, gm);
                fragB(Us[buf], n, kc, uh, um);
                MMA3B(ag[nt], ah, am, gh, gm);
                MMA3B(au[nt], ah, am, uh, um);
            }
        }
        __syncthreads();
        if (it + 2 < nit) { load_stage(buf, (it + 2) * 32); CP_COMMIT(); CP_WAIT1(); }
        else CP_WAIT0();
        __syncthreads();
    }

    const int c2 = l4 * 2;
    float* hb = g_h2 + (size_t)e * NTOK * HID_;
    #pragma unroll
    for (int nt = 0; nt < 4; nt++) {
        int r0 = bm + wm * 16 + g4;
        int col = bn + wn * 32 + nt * 8 + c2;
        float4 gg = ag[nt], uu = au[nt];
        if (r0 < cnt) {
            float s0 = gg.x / (1.f + __expf(-gg.x));
            float s1 = gg.y / (1.f + __expf(-gg.y));
            *(float2*)(hb + (size_t)r0 * HID_ + col) = make_float2(s0 * uu.x, s1 * uu.y);
        }
        if (r0 + 8 < cnt) {
            float s2 = gg.z / (1.f + __expf(-gg.z));
            float s3 = gg.w / (1.f + __expf(-gg.w));
            *(float2*)(hb + (size_t)(r0 + 8) * HID_ + col) = make_float2(s2 * uu.z, s3 * uu.w);
        }
    }
}

// ---------------- MoE down (scatter-add into residual) ----------------
__global__ __launch_bounds__(256, 2)
void moe_down_t(const float* __restrict__ wd) {
    const int e = blockIdx.z;
    const int cnt = g_cnt[e];
    const int bm = blockIdx.y * 128;
    if (bm >= cnt) return;
    const int bn = blockIdx.x * 64;
    __shared__ float As[2][128 * 32];
    __shared__ float Bs[2][64 * 32];
    const int tid = threadIdx.x, lane = tid & 31, warp = tid >> 5;
    const int wm = warp >> 1, wn = warp & 1;
    const int lrow = tid >> 3, lc4 = (tid & 7) << 2;
    const int g4 = lane >> 2, l4 = lane & 3;

    const float* Ab = g_h2 + ((size_t)e * NTOK + bm) * HID_;
    const float* Bb = wd + (size_t)e * D_ * HID_;

    float4 acc[2][4];
    #pragma unroll
    for (int i = 0; i < 2; i++)
        #pragma unroll
        for (int j = 0; j < 4; j++) acc[i][j] = make_float4(0.f, 0.f, 0.f, 0.f);

    auto load_stage = [&](int buf, int k0) {
        #pragma unroll
        for (int i = 0; i < 4; i++) {
            int row = lrow + i * 32;
            cpa16(&As[buf][swz(row, lc4)], Ab + (size_t)row * HID_ + k0 + lc4);
        }
        #pragma unroll
        for (int i = 0; i < 2; i++) {
            int row = lrow + i * 32;
            cpa16(&Bs[buf][swz(row, lc4)], Bb + (size_t)(bn + row) * HID_ + k0 + lc4);
        }
    };

    const int nit = HID_ >> 5;
    load_stage(0, 0); CP_COMMIT();
    load_stage(1, 32); CP_COMMIT();
    CP_WAIT1();
    __syncthreads();

    for (int it = 0; it < nit; it++) {
        const int buf = it & 1;
        #pragma unroll
        for (int kt2 = 0; kt2 < 2; kt2++) {
            const int kc = kt2 * 16 + l4 * 2;
            uint4 ah[2], am[2];
            #pragma unroll
            for (int mt = 0; mt < 2; mt++) fragA(As[buf], wm * 32 + mt * 16, g4, kc, ah[mt], am[mt]);
            #pragma unroll
            for (int nt = 0; nt < 4; nt++) {
                uint2 bh, bmm;
                fragB(Bs[buf], wn * 32 + nt * 8 + g4, kc, bh, bmm);
                #pragma unroll
                for (int mt = 0; mt < 2; mt++) MMA3B(acc[mt][nt], ah[mt], am[mt], bh, bmm);
            }
        }
        __syncthreads();
        if (it + 2 < nit) { load_stage(buf, (it + 2) * 32); CP_COMMIT(); CP_WAIT1(); }
        else CP_WAIT0();
        __syncthreads();
    }

    const int c2 = l4 * 2;
    #pragma unroll
    for (int mt = 0; mt < 2; mt++)
        #pragma unroll
        for (int nt = 0; nt < 4; nt++) {
            int r0 = bm + wm * 32 + mt * 16 + g4;
            int col = bn + wn * 32 + nt * 8 + c2;
            float4 a = acc[mt][nt];
            if (r0 < cnt) {
                int tok = g_idx[e * NTOK + r0];
                float sc = g_gw[e * NTOK + tok];
                atomicAdd(&g_x[(size_t)tok * D_ + col],     sc * a.x);
                atomicAdd(&g_x[(size_t)tok * D_ + col + 1], sc * a.y);
            }
            if (r0 + 8 < cnt) {
                int tok = g_idx[e * NTOK + r0 + 8];
                float sc = g_gw[e * NTOK + tok];
                atomicAdd(&g_x[(size_t)tok * D_ + col],     sc * a.z);
                atomicAdd(&g_x[(size_t)tok * D_ + col + 1], sc * a.w);
            }
        }
}

// ---------------- embed gather ----------------
__global__ void embed_k(const int* __restrict__ ids, const float* __restrict__ emb) {
    int i = blockIdx.x * 256 + threadIdx.x;
    int n = i >> 8;
    int c = i & 255;
    const float4* src = (const float4*)(emb + (size_t)ids[n] * D_) + c;
    ((float4*)g_x)[i] = *src;
}

// ---------------- rmsnorm ----------------
__global__ void rmsnorm_k(const float* __restrict__ x, const float* __restrict__ w,
                          float* __restrict__ out) {
    int row = blockIdx.x;
    int tid = threadIdx.x;  // 256
    const float* xr = x + (size_t)row * D_;
    float ss = 0.f;
    for (int i = tid; i < D_; i += 256) { float v = xr[i]; ss += v * v; }
    __shared__ float red[256];
    red[tid] = ss; __syncthreads();
    for (int s = 128; s > 0; s >>= 1) {
        if (tid < s) red[tid] += red[tid + s];
        __syncthreads();
    }
    float scale = rsqrtf(red[0] * (1.0f / D_) + 1e-6f);
    for (int i = tid; i < D_; i += 256)
        out[(size_t)row * D_ + i] = xr[i] * scale * w[i];
}

// ---------------- fused attention ----------------
__global__ void attn_k(const float* __restrict__ q, const float* __restrict__ kk,
                       const float* __restrict__ vv, float* __restrict__ out,
                       int Tk, int causal) {
    int b = blockIdx.z, h = blockIdx.y, tq = blockIdx.x;
    int tid = threadIdx.x;  // 128
    __shared__ float sq[DH];
    __shared__ float sc[TEN];
    __shared__ float red[128];
    const float* qp = q + (size_t)(b * TT + tq) * D_ + h * DH;
    if (tid < DH) sq[tid] = qp[tid];
    __syncthreads();
    int lim = causal ? (tq + 1) : Tk;
    for (int j = tid; j < Tk; j += 128) {
        float s = -1e30f;
        if (j < lim) {
            const float* kp = kk + (size_t)(b * Tk + j) * D_ + h * DH;
            float dot = 0.f;
            #pragma unroll
            for (int d = 0; d < DH; d++) dot += sq[d] * kp[d];
            s = dot * 0.125f;
        }
        sc[j] = s;
    }
    __syncthreads();
    float m = -1e30f;
    for (int j = tid; j < Tk; j += 128) m = fmaxf(m, sc[j]);
    red[tid] = m; __syncthreads();
    for (int s2 = 64; s2 > 0; s2 >>= 1) {
        if (tid < s2) red[tid] = fmaxf(red[tid], red[tid + s2]);
        __syncthreads();
    }
    float mx = red[0];
    __syncthreads();
    float ssum = 0.f;
    for (int j = tid; j < Tk; j += 128) { float e = __expf(sc[j] - mx); sc[j] = e; ssum += e; }
    red[tid] = ssum; __syncthreads();
    for (int s2 = 64; s2 > 0; s2 >>= 1) {
        if (tid < s2) red[tid] += red[tid + s2];
        __syncthreads();
    }
    float inv = 1.0f / red[0];
    __syncthreads();
    if (tid < DH) {
        float o = 0.f;
        for (int j = 0; j < lim; j++)
            o += sc[j] * vv[(size_t)(b * Tk + j) * D_ + h * DH + tid];
        out[(size_t)(b * TT + tq) * D_ + h * DH + tid] = o * inv;
    }
}

// ---------------- router ----------------
__global__ void reset_cnt_k() { if (threadIdx.x < NE) g_cnt[threadIdx.x] = 0; }

__global__ void router_k(const float* __restrict__ xn, const float* __restrict__ rw) {
    int n = blockIdx.x;
    int tid = threadIdx.x;      // 256 = 8 warps = NE experts
    int w = tid >> 5, lane = tid & 31;
    const float* xr = xn + (size_t)n * D_;
    const float* wr = rw + (size_t)w * D_;
    float dot = 0.f;
    for (int i = lane; i < D_; i += 32) dot += xr[i] * wr[i];
    #pragma unroll
    for (int o = 16; o > 0; o >>= 1) dot += __shfl_down_sync(0xffffffffu, dot, o);
    __shared__ float lg[NE];
    if (lane == 0) lg[w] = dot;
    __syncthreads();
    if (tid == 0) {
        int i1 = 0; float v1 = lg[0];
        for (int e = 1; e < NE; e++) if (lg[e] > v1) { v1 = lg[e]; i1 = e; }
        int i2 = -1; float v2 = -1e30f;
        for (int e = 0; e < NE; e++) {
            if (e == i1) continue;
            if (lg[e] > v2) { v2 = lg[e]; i2 = e; }
        }
        float e2 = __expf(v2 - v1);
        float w1 = 1.f / (1.f + e2);
        float w2 = e2 / (1.f + e2);
        g_gw[i1 * NTOK + n] = w1;
        g_gw[i2 * NTOK + n] = w2;
        int p1 = atomicAdd(&g_cnt[i1], 1); g_idx[i1 * NTOK + p1] = n;
        int p2 = atomicAdd(&g_cnt[i2], 1); g_idx[i2 * NTOK + p2] = n;
    }
}

// ---------------- host orchestration ----------------
extern "C" void kernel_launch(void* const* d_in, const int* in_sizes, int n_in,
                              void* d_out, int out_size) {
    const int*   ids  = (const int*)d_in[0];
    const float* enc  = (const float*)d_in[1];
    const float* emb  = (const float*)d_in[2];
    const float* n1   = (const float*)d_in[3];
    const float* n2   = (const float*)d_in[4];
    const float* n3   = (const float*)d_in[5];
    const float* wq_s = (const float*)d_in[6];
    const float* wk_s = (const float*)d_in[7];
    const float* wv_s = (const float*)d_in[8];
    const float* wo_s = (const float*)d_in[9];
    const float* wq_c = (const float*)d_in[10];
    const float* wk_c = (const float*)d_in[11];
    const float* wv_c = (const float*)d_in[12];
    const float* wo_c = (const float*)d_in[13];
    const float* rw   = (const float*)d_in[14];
    const float* wg   = (const float*)d_in[15];
    const float* wu   = (const float*)d_in[16];
    const float* wd   = (const float*)d_in[17];
    const float* fn   = (const float*)d_in[18];
    const float* hw   = (const float*)d_in[19];
    float* out = (float*)d_out;

    float *x, *xn, *q, *k, *v, *ao;
    cudaGetSymbolAddress((void**)&x,  g_x);
    cudaGetSymbolAddress((void**)&xn, g_xn);
    cudaGetSymbolAddress((void**)&q,  g_q);
    cudaGetSymbolAddress((void**)&k,  g_k);
    cudaGetSymbolAddress((void**)&v,  g_v);
    cudaGetSymbolAddress((void**)&ao, g_ao);

    const size_t DD = (size_t)D_ * D_;
    const dim3 gNN(D_ / 64, NTOK / 128);        // 16 x 8
    const dim3 gNN3(D_ / 64, NTOK / 128, 3);    // QKV fused
    const dim3 gKV2(D_ / 64, NKV / 128, 2);     // cross K,V fused

    embed_k<<<NTOK, 256>>>(ids, emb);

    for (int l = 0; l < NL_; l++) {
        // ---- self attention ----
        rmsnorm_k<<<NTOK, 256>>>(x, n1 + l * D_, xn);
        gemm_t3<0><<<gNN3, 256>>>(xn, wq_s + l * DD, wk_s + l * DD, wv_s + l * DD,
                                  q, k, v, NTOK, D_, D_);
        attn_k<<<dim3(TT, H_, BB), 128>>>(q, k, v, ao, TT, 1);
        gemm_t<1><<<gNN, 256>>>(ao, wo_s + l * DD, x, NTOK, D_, D_);

        // ---- cross attention ----
        rmsnorm_k<<<NTOK, 256>>>(x, n2 + l * D_, xn);
        gemm_t<0><<<gNN, 256>>>(xn, wq_c + l * DD, q, NTOK, D_, D_);
        gemm_t3<0><<<gKV2, 256>>>(enc, wk_c + l * DD, wv_c + l * DD, wv_c + l * DD,
                                  k, v, v, NKV, D_, D_);
        attn_k<<<dim3(TT, H_, BB), 128>>>(q, k, v, ao, TEN, 0);
        gemm_t<1><<<gNN, 256>>>(ao, wo_c + l * DD, x, NTOK, D_, D_);

        // ---- MoE ----
        rmsnorm_k<<<NTOK, 256>>>(x, n3 + l * D_, xn);
        reset_cnt_k<<<1, 32>>>();
        router_k<<<NTOK, 256>>>(xn, rw + (size_t)l * NE * D_);
        moe_gateup_t<<<dim3(HID_ / 64, NTOK / 64, NE), 256>>>(
            xn, wg + (size_t)l * NE * HID_ * D_, wu + (size_t)l * NE * HID_ * D_);
        moe_down_t<<<dim3(D_ / 64, NTOK / 128, NE), 256>>>(
            wd + (size_t)l * NE * D_ * HID_);
    }

    // ---- final norm + heads (3 levels fused) ----
    rmsnorm_k<<<NTOK, 256>>>(x, fn, xn);
    gemm_t3<0><<<dim3(KCB / 64, NTOK / 128, 3), 256>>>(
        xn, hw, hw + (size_t)KCB * D_, hw + 2 * (size_t)KCB * D_,
        out, out + (size_t)NTOK * KCB, out + 2 * (size_t)NTOK * KCB,
        NTOK, KCB, D_);
}